// round 3
// baseline (speedup 1.0000x reference)
#include <cuda_runtime.h>

#define B_SZ 8
#define T_SEQ 2048
#define C_DIM 1024
#define H_DIM 64
#define NEG_BIG (-1e30f)

// Scratch (allocation-free): q,k,v projections + per-(b,s) column softmax stats.
__device__ float g_q[B_SZ * T_SEQ * H_DIM];
__device__ float g_k[B_SZ * T_SEQ * H_DIM];
__device__ float g_v[B_SZ * T_SEQ * H_DIM];
__device__ float g_m[B_SZ * T_SEQ];      // column max
__device__ float g_invd[B_SZ * T_SEQ];   // 1 / column sum

// ---------------------------------------------------------------------------
// Kernel 1: QKV projection. out[row,h] = sum_c x[row,c] * W[h,c]
// grid = (M/128, 3), block = 256. BM=128, BN=64, BK=32.
// Thread (tr,tc): tr=tid/16 owns 8 rows, tc=tid%16 owns 4 cols -> 8x4 microtile.
// ---------------------------------------------------------------------------
__global__ __launch_bounds__(256) void qkv_kernel(
    const float* __restrict__ x,
    const float* __restrict__ Wq,
    const float* __restrict__ Wk,
    const float* __restrict__ Wv)
{
    __shared__ float xs[128][33];
    __shared__ float ws[64][33];

    const float* W = (blockIdx.y == 0) ? Wq : (blockIdx.y == 1) ? Wk : Wv;
    float* out = (blockIdx.y == 0) ? g_q : (blockIdx.y == 1) ? g_k : g_v;

    const int row0 = blockIdx.x * 128;
    const int tid = threadIdx.x;
    const int tr = tid >> 4;   // 0..15
    const int tc = tid & 15;   // 0..15

    float acc[8][4];
#pragma unroll
    for (int i = 0; i < 8; i++)
#pragma unroll
        for (int j = 0; j < 4; j++) acc[i][j] = 0.f;

    for (int k0 = 0; k0 < C_DIM; k0 += 32) {
        // x tile 128x32 (4096 floats): 4 x float4 per thread
#pragma unroll
        for (int i = 0; i < 4; i++) {
            int e = tid * 4 + i * 1024;
            int r = e >> 5, c = e & 31;
            float4 v4 = *(const float4*)(x + (size_t)(row0 + r) * C_DIM + k0 + c);
            xs[r][c + 0] = v4.x; xs[r][c + 1] = v4.y;
            xs[r][c + 2] = v4.z; xs[r][c + 3] = v4.w;
        }
        // W tile 64x32 (2048 floats): 2 x float4 per thread
#pragma unroll
        for (int i = 0; i < 2; i++) {
            int e = tid * 4 + i * 1024;
            int r = e >> 5, c = e & 31;
            float4 v4 = *(const float4*)(W + (size_t)r * C_DIM + k0 + c);
            ws[r][c + 0] = v4.x; ws[r][c + 1] = v4.y;
            ws[r][c + 2] = v4.z; ws[r][c + 3] = v4.w;
        }
        __syncthreads();

#pragma unroll
        for (int kk = 0; kk < 32; kk++) {
            float a[8], b[4];
#pragma unroll
            for (int i = 0; i < 8; i++) a[i] = xs[tr * 8 + i][kk];
#pragma unroll
            for (int j = 0; j < 4; j++) b[j] = ws[tc * 4 + j][kk];
#pragma unroll
            for (int i = 0; i < 8; i++)
#pragma unroll
                for (int j = 0; j < 4; j++) acc[i][j] = fmaf(a[i], b[j], acc[i][j]);
        }
        __syncthreads();
    }

#pragma unroll
    for (int i = 0; i < 8; i++)
#pragma unroll
        for (int j = 0; j < 4; j++)
            out[(size_t)(row0 + tr * 8 + i) * H_DIM + tc * 4 + j] = acc[i][j];
}

// ---------------------------------------------------------------------------
// Kernel 2: column softmax stats. For each (b, s):
//   m[s] = max_{t>=s} (q[t]·k[s] * 0.125),  d[s] = sum exp(aff - m)
// grid = (T/64, B), block = 256. Block owns 64 key-columns, loops t-tiles of 64
// starting at the diagonal. Thread (tr,tc): rows t_local=tr*4+i, cols tc+16j, j<4.
// ---------------------------------------------------------------------------
__global__ __launch_bounds__(256) void colstats_kernel()
{
    __shared__ float ks[64][65];
    __shared__ float qs[64][65];
    __shared__ float red_m[16][64];
    __shared__ float red_d[16][64];

    const int b = blockIdx.y;
    const int s0 = blockIdx.x * 64;
    const int tid = threadIdx.x;
    const int tr = tid >> 4;
    const int tc = tid & 15;

    const float* kb = g_k + (size_t)b * T_SEQ * H_DIM;
    const float* qb = g_q + (size_t)b * T_SEQ * H_DIM;

    // load k tile (rows s0..s0+63), 16 floats/thread
    {
        int r = tid >> 2, c = (tid & 3) * 16;
#pragma unroll
        for (int i = 0; i < 4; i++) {
            float4 v4 = *(const float4*)(kb + (size_t)(s0 + r) * H_DIM + c + 4 * i);
            ks[r][c + 4 * i + 0] = v4.x; ks[r][c + 4 * i + 1] = v4.y;
            ks[r][c + 4 * i + 2] = v4.z; ks[r][c + 4 * i + 3] = v4.w;
        }
    }
    __syncthreads();

    float m[4], d[4];
#pragma unroll
    for (int j = 0; j < 4; j++) { m[j] = NEG_BIG; d[j] = 0.f; }

    for (int tt = blockIdx.x; tt < T_SEQ / 64; tt++) {
        const int t0 = tt * 64;
        // load q tile
        {
            int r = tid >> 2, c = (tid & 3) * 16;
#pragma unroll
            for (int i = 0; i < 4; i++) {
                float4 v4 = *(const float4*)(qb + (size_t)(t0 + r) * H_DIM + c + 4 * i);
                qs[r][c + 4 * i + 0] = v4.x; qs[r][c + 4 * i + 1] = v4.y;
                qs[r][c + 4 * i + 2] = v4.z; qs[r][c + 4 * i + 3] = v4.w;
            }
        }
        __syncthreads();

        float sc[4][4];
#pragma unroll
        for (int i = 0; i < 4; i++)
#pragma unroll
            for (int j = 0; j < 4; j++) sc[i][j] = 0.f;

#pragma unroll 8
        for (int kk = 0; kk < 64; kk++) {
            float a[4], bb[4];
#pragma unroll
            for (int i = 0; i < 4; i++) a[i] = qs[tr * 4 + i][kk];
#pragma unroll
            for (int j = 0; j < 4; j++) bb[j] = ks[tc + 16 * j][kk];
#pragma unroll
            for (int i = 0; i < 4; i++)
#pragma unroll
                for (int j = 0; j < 4; j++) sc[i][j] = fmaf(a[i], bb[j], sc[i][j]);
        }

        const bool diag = (tt == blockIdx.x);
#pragma unroll
        for (int j = 0; j < 4; j++) {
            const int s = s0 + tc + 16 * j;
#pragma unroll
            for (int i = 0; i < 4; i++) {
                const int t = t0 + tr * 4 + i;
                if (!diag || t >= s) {
                    float v = sc[i][j] * 0.125f;
                    float nm = fmaxf(m[j], v);
                    d[j] = d[j] * __expf(m[j] - nm) + __expf(v - nm);
                    m[j] = nm;
                }
            }
        }
        __syncthreads();   // protect qs before next iteration's load
    }

    // cross-thread reduction over the 16 tr groups per column
#pragma unroll
    for (int j = 0; j < 4; j++) {
        red_m[tr][tc + 16 * j] = m[j];
        red_d[tr][tc + 16 * j] = d[j];
    }
    __syncthreads();

    if (tid < 64) {
        float mm = NEG_BIG, dd = 0.f;
#pragma unroll
        for (int r = 0; r < 16; r++) {
            float mi = red_m[r][tid], di = red_d[r][tid];
            float nm = fmaxf(mm, mi);
            dd = dd * __expf(mm - nm) + di * __expf(mi - nm);
            mm = nm;
        }
        g_m[(size_t)b * T_SEQ + s0 + tid] = mm;
        g_invd[(size_t)b * T_SEQ + s0 + tid] = 1.0f / dd;
    }
}

// ---------------------------------------------------------------------------
// Kernel 3: output. out[t,h] = sum_{s<=t} exp(q[t]·k[s]*0.125 - m[s]) * invd[s] * v[s,h]
// grid = (T/64, B), block = 256. Block owns 64 query rows x 64 h.
// Loops key-tiles of 32 (only s-tiles intersecting s<=t).
// ---------------------------------------------------------------------------
__global__ __launch_bounds__(256) void out_kernel(float* __restrict__ out)
{
    __shared__ float qs[64][65];
    __shared__ float ks[32][65];
    __shared__ float vs[32][65];
    __shared__ float ps[64][33];
    __shared__ float sm_m[32], sm_id[32];

    const int b = blockIdx.y;
    const int t0 = blockIdx.x * 64;
    const int tid = threadIdx.x;
    const int tr = tid >> 4;
    const int tc = tid & 15;

    const float* qb = g_q + (size_t)b * T_SEQ * H_DIM;
    const float* kb = g_k + (size_t)b * T_SEQ * H_DIM;
    const float* vb = g_v + (size_t)b * T_SEQ * H_DIM;

    // load q tile (64 rows)
    {
        int r = tid >> 2, c = (tid & 3) * 16;
#pragma unroll
        for (int i = 0; i < 4; i++) {
            float4 v4 = *(const float4*)(qb + (size_t)(t0 + r) * H_DIM + c + 4 * i);
            qs[r][c + 4 * i + 0] = v4.x; qs[r][c + 4 * i + 1] = v4.y;
            qs[r][c + 4 * i + 2] = v4.z; qs[r][c + 4 * i + 3] = v4.w;
        }
    }

    float acc[4][4];
#pragma unroll
    for (int i = 0; i < 4; i++)
#pragma unroll
        for (int j = 0; j < 4; j++) acc[i][j] = 0.f;

    __syncthreads();

    const int n_stile = 2 * blockIdx.x + 2;   // s-tiles of 32 covering s <= t0+63
    for (int st = 0; st < n_stile; st++) {
        const int s0 = st * 32;
        // load k/v tiles 32x64, 8 floats/thread each
        {
            int r = tid >> 3, c = (tid & 7) * 8;
#pragma unroll
            for (int h = 0; h < 2; h++) {
                float4 v4 = *(const float4*)(kb + (size_t)(s0 + r) * H_DIM + c + 4 * h);
                ks[r][c + 4 * h + 0] = v4.x; ks[r][c + 4 * h + 1] = v4.y;
                ks[r][c + 4 * h + 2] = v4.z; ks[r][c + 4 * h + 3] = v4.w;
                float4 w4 = *(const float4*)(vb + (size_t)(s0 + r) * H_DIM + c + 4 * h);
                vs[r][c + 4 * h + 0] = w4.x; vs[r][c + 4 * h + 1] = w4.y;
                vs[r][c + 4 * h + 2] = w4.z; vs[r][c + 4 * h + 3] = w4.w;
            }
        }
        if (tid < 32) {
            sm_m[tid] = g_m[(size_t)b * T_SEQ + s0 + tid];
            sm_id[tid] = g_invd[(size_t)b * T_SEQ + s0 + tid];
        }
        __syncthreads();

        // gemm1: scores 64x32. t_local = tr*4+i, s_local = tc+16j (j<2)
        float sc[4][2];
#pragma unroll
        for (int i = 0; i < 4; i++)
#pragma unroll
            for (int j = 0; j < 2; j++) sc[i][j] = 0.f;

#pragma unroll 8
        for (int kk = 0; kk < 64; kk++) {
            float a[4], bb[2];
#pragma unroll
            for (int i = 0; i < 4; i++) a[i] = qs[tr * 4 + i][kk];
#pragma unroll
            for (int j = 0; j < 2; j++) bb[j] = ks[tc + 16 * j][kk];
#pragma unroll
            for (int i = 0; i < 4; i++)
#pragma unroll
                for (int j = 0; j < 2; j++) sc[i][j] = fmaf(a[i], bb[j], sc[i][j]);
        }

        // exp -> probabilities into smem
#pragma unroll
        for (int j = 0; j < 2; j++) {
            const int sl = tc + 16 * j;
            const int s = s0 + sl;
#pragma unroll
            for (int i = 0; i < 4; i++) {
                const int t = t0 + tr * 4 + i;
                float p = 0.f;
                if (t >= s)
                    p = __expf(sc[i][j] * 0.125f - sm_m[sl]) * sm_id[sl];
                ps[tr * 4 + i][sl] = p;
            }
        }
        __syncthreads();

        // gemm2: acc += ps[64x32] @ vs[32x64]. h cols = tc+16j (j<4)
#pragma unroll 4
        for (int ss = 0; ss < 32; ss++) {
            float pv[4], vv[4];
#pragma unroll
            for (int i = 0; i < 4; i++) pv[i] = ps[tr * 4 + i][ss];
#pragma unroll
            for (int j = 0; j < 4; j++) vv[j] = vs[ss][tc + 16 * j];
#pragma unroll
            for (int i = 0; i < 4; i++)
#pragma unroll
                for (int j = 0; j < 4; j++) acc[i][j] = fmaf(pv[i], vv[j], acc[i][j]);
        }
        __syncthreads();
    }

#pragma unroll
    for (int i = 0; i < 4; i++)
#pragma unroll
        for (int j = 0; j < 4; j++)
            out[(size_t)(b * T_SEQ + t0 + tr * 4 + i) * H_DIM + tc + 16 * j] = acc[i][j];
}

extern "C" void kernel_launch(void* const* d_in, const int* in_sizes, int n_in,
                              void* d_out, int out_size)
{
    const float* x  = (const float*)d_in[0];
    const float* Wq = (const float*)d_in[1];
    const float* Wk = (const float*)d_in[2];
    const float* Wv = (const float*)d_in[3];
    float* out = (float*)d_out;

    qkv_kernel<<<dim3(128, 3), 256>>>(x, Wq, Wk, Wv);
    colstats_kernel<<<dim3(T_SEQ / 64, B_SZ), 256>>>();
    out_kernel<<<dim3(T_SEQ / 64, B_SZ), 256>>>(out);
}

// round 4
// speedup vs baseline: 2.1154x; 2.1154x over previous
#include <cuda_runtime.h>
#include <cuda_bf16.h>

#define B_SZ 8
#define T_SEQ 2048
#define C_DIM 1024
#define H_DIM 64
#define BT (B_SZ * T_SEQ)

// Scratch (u32-packed bf16x2 so all accesses are 4B-aligned)
__device__ unsigned g_qh[BT * 32], g_ql[BT * 32];
__device__ unsigned g_kh[BT * 32], g_kl[BT * 32];
__device__ unsigned g_vth[B_SZ * 64 * (T_SEQ / 2)], g_vtl[B_SZ * 64 * (T_SEQ / 2)]; // [b][h][s/2]
__device__ float g_vraw[BT * 64];
__device__ float g_invd[BT];

__device__ __forceinline__ void mma_bf16(float* c, const unsigned* a, const unsigned* b)
{
    asm volatile(
        "mma.sync.aligned.m16n8k16.row.col.f32.bf16.bf16.f32 "
        "{%0,%1,%2,%3}, {%4,%5,%6,%7}, {%8,%9}, {%0,%1,%2,%3};"
        : "+f"(c[0]), "+f"(c[1]), "+f"(c[2]), "+f"(c[3])
        : "r"(a[0]), "r"(a[1]), "r"(a[2]), "r"(a[3]), "r"(b[0]), "r"(b[1]));
}

// split two floats into packed bf16x2 (hi) and packed bf16x2 residual (lo)
__device__ __forceinline__ void split2(float x, float y, unsigned& hi, unsigned& lo)
{
    __nv_bfloat16 xh = __float2bfloat16(x);
    __nv_bfloat16 yh = __float2bfloat16(y);
    float xr = x - __bfloat162float(xh);
    float yr = y - __bfloat162float(yh);
    hi = (unsigned)__bfloat16_as_ushort(xh) | ((unsigned)__bfloat16_as_ushort(yh) << 16);
    lo = (unsigned)__bfloat16_as_ushort(__float2bfloat16(xr)) |
         ((unsigned)__bfloat16_as_ushort(__float2bfloat16(yr)) << 16);
}

// ---------------------------------------------------------------------------
// Kernel 1: fused QKV projection on tensor cores.
// grid = (128), block = 256 (8 warps). Block: 128 rows x 192 cols (q|k|v).
// Warp w: rows [32*(w&3), +32) (2 m16 tiles), n-frags 12*(w>>2)..+12.
// K-chunks of 32; x and W split to bf16 hi/lo in smem on the fly.
// ---------------------------------------------------------------------------
#define PB 18  // u32 pitch for 32-col bf16 rows (+4 pad)

__global__ __launch_bounds__(256) void qkv_mma(
    const float* __restrict__ x,
    const float* __restrict__ Wq,
    const float* __restrict__ Wk,
    const float* __restrict__ Wv)
{
    __shared__ unsigned xs_h[128 * PB], xs_l[128 * PB];
    __shared__ unsigned ws_h[192 * PB], ws_l[192 * PB];

    const int tid = threadIdx.x, lane = tid & 31, w = tid >> 5;
    const int g = lane >> 2, t4 = lane & 3;
    const int row0 = blockIdx.x * 128;
    const int mrow = 32 * (w & 3);
    const int nf0 = 12 * (w >> 2);

    float acc[2][12][4];
#pragma unroll
    for (int mt = 0; mt < 2; mt++)
#pragma unroll
        for (int nf = 0; nf < 12; nf++)
#pragma unroll
            for (int e = 0; e < 4; e++) acc[mt][nf][e] = 0.f;

    for (int kc = 0; kc < C_DIM; kc += 32) {
        __syncthreads();
        // x tile 128x32
#pragma unroll
        for (int i = 0; i < 4; i++) {
            int e = tid * 4 + i * 1024;
            int r = e >> 5, c = e & 31;
            float4 v = *(const float4*)(x + (size_t)(row0 + r) * C_DIM + kc + c);
            unsigned h0, l0, h1, l1;
            split2(v.x, v.y, h0, l0);
            split2(v.z, v.w, h1, l1);
            xs_h[r * PB + (c >> 1)] = h0; xs_h[r * PB + (c >> 1) + 1] = h1;
            xs_l[r * PB + (c >> 1)] = l0; xs_l[r * PB + (c >> 1) + 1] = l1;
        }
        // W tile 192x32 (q rows 0-63, k 64-127, v 128-191)
#pragma unroll
        for (int i = 0; i < 6; i++) {
            int e = tid * 4 + i * 1024;
            int r = e >> 5, c = e & 31;
            const float* Wp = (r < 64) ? (Wq + (size_t)r * C_DIM)
                            : (r < 128) ? (Wk + (size_t)(r - 64) * C_DIM)
                                        : (Wv + (size_t)(r - 128) * C_DIM);
            float4 v = *(const float4*)(Wp + kc + c);
            unsigned h0, l0, h1, l1;
            split2(v.x, v.y, h0, l0);
            split2(v.z, v.w, h1, l1);
            ws_h[r * PB + (c >> 1)] = h0; ws_h[r * PB + (c >> 1) + 1] = h1;
            ws_l[r * PB + (c >> 1)] = l0; ws_l[r * PB + (c >> 1) + 1] = l1;
        }
        __syncthreads();

#pragma unroll
        for (int ks = 0; ks < 2; ks++) {
            unsigned ah[2][4], al[2][4];
#pragma unroll
            for (int mt = 0; mt < 2; mt++) {
                int r = mrow + 16 * mt + g;
                int cu = 8 * ks + t4;
                ah[mt][0] = xs_h[r * PB + cu];       ah[mt][1] = xs_h[(r + 8) * PB + cu];
                ah[mt][2] = xs_h[r * PB + cu + 4];   ah[mt][3] = xs_h[(r + 8) * PB + cu + 4];
                al[mt][0] = xs_l[r * PB + cu];       al[mt][1] = xs_l[(r + 8) * PB + cu];
                al[mt][2] = xs_l[r * PB + cu + 4];   al[mt][3] = xs_l[(r + 8) * PB + cu + 4];
            }
#pragma unroll
            for (int nf = 0; nf < 12; nf++) {
                int hrow = 8 * (nf0 + nf) + g;
                int cu = 8 * ks + t4;
                unsigned bh[2], bl[2];
                bh[0] = ws_h[hrow * PB + cu]; bh[1] = ws_h[hrow * PB + cu + 4];
                bl[0] = ws_l[hrow * PB + cu]; bl[1] = ws_l[hrow * PB + cu + 4];
#pragma unroll
                for (int mt = 0; mt < 2; mt++) {
                    mma_bf16(acc[mt][nf], ah[mt], bh);
                    mma_bf16(acc[mt][nf], ah[mt], bl);
                    mma_bf16(acc[mt][nf], al[mt], bh);
                }
            }
        }
    }

    // epilogue: q,k -> bf16 hi/lo packed; v -> fp32
#pragma unroll
    for (int mt = 0; mt < 2; mt++) {
#pragma unroll
        for (int nf = 0; nf < 12; nf++) {
            int col = 8 * (nf0 + nf) + 2 * t4;
            size_t r0g = (size_t)(row0 + mrow + 16 * mt + g);
            float c0 = acc[mt][nf][0], c1 = acc[mt][nf][1];
            float c2 = acc[mt][nf][2], c3 = acc[mt][nf][3];
            if (col < 64) {
                unsigned h, l;
                split2(c0, c1, h, l);
                g_qh[r0g * 32 + (col >> 1)] = h; g_ql[r0g * 32 + (col >> 1)] = l;
                split2(c2, c3, h, l);
                g_qh[(r0g + 8) * 32 + (col >> 1)] = h; g_ql[(r0g + 8) * 32 + (col >> 1)] = l;
            } else if (col < 128) {
                int kc2 = (col - 64) >> 1;
                unsigned h, l;
                split2(c0, c1, h, l);
                g_kh[r0g * 32 + kc2] = h; g_kl[r0g * 32 + kc2] = l;
                split2(c2, c3, h, l);
                g_kh[(r0g + 8) * 32 + kc2] = h; g_kl[(r0g + 8) * 32 + kc2] = l;
            } else {
                int vc = col - 128;
                *(float2*)&g_vraw[r0g * 64 + vc] = make_float2(c0, c1);
                *(float2*)&g_vraw[(r0g + 8) * 64 + vc] = make_float2(c2, c3);
            }
        }
    }
}

// ---------------------------------------------------------------------------
// Kernel 2: column softmax denominators (no max subtraction needed here:
// |aff| <~ 20 so exp stays comfortably in fp32 range).
// d[s] = sum_{t>=s} exp(q[t].k[s]/8);  writes g_invd = 1/d.
// grid = (32, B), block = 256 (8 warps): warp = (m-tile w&3) x (n-half w>>2).
// ---------------------------------------------------------------------------
#define PC 36  // u32 pitch for 64-col bf16 rows (+8 pad)

__global__ __launch_bounds__(256) void colstats_mma()
{
    __shared__ unsigned ks_h[64 * PC], ks_l[64 * PC];
    __shared__ unsigned qs_h[64 * PC], qs_l[64 * PC];
    __shared__ float red[8][64];

    const int b = blockIdx.y;
    const int s0 = blockIdx.x * 64;
    const int tid = threadIdx.x, lane = tid & 31, w = tid >> 5;
    const int g = lane >> 2, t4 = lane & 3;
    const int mt = w & 3, nh = w >> 2;

    const unsigned* kh = g_kh + (size_t)b * T_SEQ * 32;
    const unsigned* kl = g_kl + (size_t)b * T_SEQ * 32;
    const unsigned* qh = g_qh + (size_t)b * T_SEQ * 32;
    const unsigned* ql = g_ql + (size_t)b * T_SEQ * 32;

    for (int idx = tid; idx < 2048; idx += 256) {
        int r = idx >> 5, c = idx & 31;
        ks_h[r * PC + c] = kh[(size_t)(s0 + r) * 32 + c];
        ks_l[r * PC + c] = kl[(size_t)(s0 + r) * 32 + c];
    }

    float dp[8];
#pragma unroll
    for (int i = 0; i < 8; i++) dp[i] = 0.f;

    for (int tt = blockIdx.x; tt < T_SEQ / 64; tt++) {
        const int t0 = tt * 64;
        __syncthreads();
        for (int idx = tid; idx < 2048; idx += 256) {
            int r = idx >> 5, c = idx & 31;
            qs_h[r * PC + c] = qh[(size_t)(t0 + r) * 32 + c];
            qs_l[r * PC + c] = ql[(size_t)(t0 + r) * 32 + c];
        }
        __syncthreads();

        unsigned ah[4][4], al[4][4];
#pragma unroll
        for (int ksi = 0; ksi < 4; ksi++) {
            int r = 16 * mt + g;
            int cu = 8 * ksi + t4;
            ah[ksi][0] = qs_h[r * PC + cu];     ah[ksi][1] = qs_h[(r + 8) * PC + cu];
            ah[ksi][2] = qs_h[r * PC + cu + 4]; ah[ksi][3] = qs_h[(r + 8) * PC + cu + 4];
            al[ksi][0] = qs_l[r * PC + cu];     al[ksi][1] = qs_l[(r + 8) * PC + cu];
            al[ksi][2] = qs_l[r * PC + cu + 4]; al[ksi][3] = qs_l[(r + 8) * PC + cu + 4];
        }

#pragma unroll
        for (int nf = 0; nf < 4; nf++) {
            float S[4] = {0.f, 0.f, 0.f, 0.f};
            int srow = 32 * nh + 8 * nf + g;
#pragma unroll
            for (int ksi = 0; ksi < 4; ksi++) {
                unsigned bh[2], bl[2];
                int cu = 8 * ksi + t4;
                bh[0] = ks_h[srow * PC + cu]; bh[1] = ks_h[srow * PC + cu + 4];
                bl[0] = ks_l[srow * PC + cu]; bl[1] = ks_l[srow * PC + cu + 4];
                mma_bf16(S, ah[ksi], bh);
                mma_bf16(S, ah[ksi], bl);
                mma_bf16(S, al[ksi], bh);
            }
            int scol = s0 + 32 * nh + 8 * nf + 2 * t4;
            int trow = t0 + 16 * mt + g;
            if (trow >= scol)         dp[2 * nf]     += __expf(S[0] * 0.125f);
            if (trow >= scol + 1)     dp[2 * nf + 1] += __expf(S[1] * 0.125f);
            if (trow + 8 >= scol)     dp[2 * nf]     += __expf(S[2] * 0.125f);
            if (trow + 8 >= scol + 1) dp[2 * nf + 1] += __expf(S[3] * 0.125f);
        }
    }

#pragma unroll
    for (int i = 0; i < 8; i++) {
        dp[i] += __shfl_xor_sync(0xffffffffu, dp[i], 4);
        dp[i] += __shfl_xor_sync(0xffffffffu, dp[i], 8);
        dp[i] += __shfl_xor_sync(0xffffffffu, dp[i], 16);
    }
    if (lane < 4) {
#pragma unroll
        for (int nf = 0; nf < 4; nf++) {
            red[w][32 * nh + 8 * nf + 2 * lane]     = dp[2 * nf];
            red[w][32 * nh + 8 * nf + 2 * lane + 1] = dp[2 * nf + 1];
        }
    }
    __syncthreads();
    if (tid < 64) {
        int base = (tid < 32) ? 0 : 4;
        float d = red[base][tid] + red[base + 1][tid] + red[base + 2][tid] + red[base + 3][tid];
        g_invd[(size_t)b * T_SEQ + s0 + tid] = 1.0f / d;
    }
}

// ---------------------------------------------------------------------------
// Kernel 3: v'[s,h] = v[s,h] * invd[s], stored TRANSPOSED [b][h][s] as hi/lo.
// grid = (32, B), block = 256.
// ---------------------------------------------------------------------------
__global__ __launch_bounds__(256) void vscale_kernel()
{
    __shared__ float tile[64][65];
    const int b = blockIdx.y;
    const int s0 = blockIdx.x * 64;
    const int tid = threadIdx.x;

    for (int idx = tid; idx < 4096; idx += 256) {
        int s = idx >> 6, h = idx & 63;
        tile[s][h] = g_vraw[((size_t)b * T_SEQ + s0 + s) * 64 + h] *
                     g_invd[(size_t)b * T_SEQ + s0 + s];
    }
    __syncthreads();
    for (int idx = tid; idx < 2048; idx += 256) {
        int h = idx >> 5, sp = idx & 31;
        unsigned hi, lo;
        split2(tile[2 * sp][h], tile[2 * sp + 1][h], hi, lo);
        size_t o = ((size_t)b * 64 + h) * (T_SEQ / 2) + (s0 >> 1) + sp;
        g_vth[o] = hi;
        g_vtl[o] = lo;
    }
}

// ---------------------------------------------------------------------------
// Kernel 4: out[t,h] = sum_{s<=t} exp(q[t].k[s]/8) * v'[s,h]
// grid = (16, B), block = 256 (8 warps, each one m16 tile of the 128-row block).
// Q fragments live in registers across the whole s loop.
// ---------------------------------------------------------------------------
__global__ __launch_bounds__(256) void out_mma(float* __restrict__ out)
{
    __shared__ unsigned ks_h[64 * PC], ks_l[64 * PC];
    __shared__ unsigned vs_h[64 * PC], vs_l[64 * PC];

    const int b = blockIdx.y;
    const int t0 = blockIdx.x * 128;
    const int tid = threadIdx.x, lane = tid & 31, w = tid >> 5;
    const int g = lane >> 2, t4 = lane & 3;

    const unsigned* qh = g_qh + (size_t)b * T_SEQ * 32;
    const unsigned* ql = g_ql + (size_t)b * T_SEQ * 32;
    const unsigned* kh = g_kh + (size_t)b * T_SEQ * 32;
    const unsigned* kl = g_kl + (size_t)b * T_SEQ * 32;
    const unsigned* vth = g_vth + (size_t)b * 64 * (T_SEQ / 2);
    const unsigned* vtl = g_vtl + (size_t)b * 64 * (T_SEQ / 2);

    const int trow = t0 + 16 * w + g;

    unsigned aqh[4][4], aql[4][4];
#pragma unroll
    for (int ksi = 0; ksi < 4; ksi++) {
        int cu = 8 * ksi + t4;
        aqh[ksi][0] = qh[(size_t)trow * 32 + cu];
        aqh[ksi][1] = qh[(size_t)(trow + 8) * 32 + cu];
        aqh[ksi][2] = qh[(size_t)trow * 32 + cu + 4];
        aqh[ksi][3] = qh[(size_t)(trow + 8) * 32 + cu + 4];
        aql[ksi][0] = ql[(size_t)trow * 32 + cu];
        aql[ksi][1] = ql[(size_t)(trow + 8) * 32 + cu];
        aql[ksi][2] = ql[(size_t)trow * 32 + cu + 4];
        aql[ksi][3] = ql[(size_t)(trow + 8) * 32 + cu + 4];
    }

    float acc[8][4];
#pragma unroll
    for (int nf = 0; nf < 8; nf++)
#pragma unroll
        for (int e = 0; e < 4; e++) acc[nf][e] = 0.f;

    const int ns = 2 * blockIdx.x + 2;
    for (int si = 0; si < ns; si++) {
        const int s0 = si * 64;
        __syncthreads();
        for (int idx = tid; idx < 2048; idx += 256) {
            int r = idx >> 5, c = idx & 31;
            ks_h[r * PC + c] = kh[(size_t)(s0 + r) * 32 + c];
            ks_l[r * PC + c] = kl[(size_t)(s0 + r) * 32 + c];
            vs_h[r * PC + c] = vth[(size_t)r * (T_SEQ / 2) + (s0 >> 1) + c];
            vs_l[r * PC + c] = vtl[(size_t)r * (T_SEQ / 2) + (s0 >> 1) + c];
        }
        __syncthreads();

        // S = Q K^T (64 s-cols)
        float S[8][4];
#pragma unroll
        for (int nf = 0; nf < 8; nf++) {
#pragma unroll
            for (int e = 0; e < 4; e++) S[nf][e] = 0.f;
            int srow = 8 * nf + g;
#pragma unroll
            for (int ksi = 0; ksi < 4; ksi++) {
                unsigned bh[2], bl[2];
                int cu = 8 * ksi + t4;
                bh[0] = ks_h[srow * PC + cu]; bh[1] = ks_h[srow * PC + cu + 4];
                bl[0] = ks_l[srow * PC + cu]; bl[1] = ks_l[srow * PC + cu + 4];
                mma_bf16(S[nf], aqh[ksi], bh);
                mma_bf16(S[nf], aqh[ksi], bl);
                mma_bf16(S[nf], aql[ksi], bh);
            }
        }

        // p = exp(S/8) masked to s<=t; repack as A-fragments (hi/lo)
        unsigned ph[4][4], pl[4][4];
#pragma unroll
        for (int fp = 0; fp < 4; fp++) {
#pragma unroll
            for (int half = 0; half < 2; half++) {
                int nf = 2 * fp + half;
                int sc = s0 + 8 * nf + 2 * t4;
                float p0 = (sc     <= trow)     ? __expf(S[nf][0] * 0.125f) : 0.f;
                float p1 = (sc + 1 <= trow)     ? __expf(S[nf][1] * 0.125f) : 0.f;
                float p2 = (sc     <= trow + 8) ? __expf(S[nf][2] * 0.125f) : 0.f;
                float p3 = (sc + 1 <= trow + 8) ? __expf(S[nf][3] * 0.125f) : 0.f;
                unsigned h01, l01, h23, l23;
                split2(p0, p1, h01, l01);
                split2(p2, p3, h23, l23);
                ph[fp][2 * half] = h01; ph[fp][2 * half + 1] = h23;
                pl[fp][2 * half] = l01; pl[fp][2 * half + 1] = l23;
            }
        }

        // acc += P @ V'
#pragma unroll
        for (int nf = 0; nf < 8; nf++) {
            int hrow = 8 * nf + g;
#pragma unroll
            for (int kp = 0; kp < 4; kp++) {
                unsigned bh[2], bl[2];
                int cu = 8 * kp + t4;
                bh[0] = vs_h[hrow * PC + cu]; bh[1] = vs_h[hrow * PC + cu + 4];
                bl[0] = vs_l[hrow * PC + cu]; bl[1] = vs_l[hrow * PC + cu + 4];
                mma_bf16(acc[nf], ph[kp], bh);
                mma_bf16(acc[nf], ph[kp], bl);
                mma_bf16(acc[nf], pl[kp], bh);
            }
        }
    }

#pragma unroll
    for (int nf = 0; nf < 8; nf++) {
        int col = 8 * nf + 2 * t4;
        *(float2*)&out[((size_t)b * T_SEQ + trow) * 64 + col] =
            make_float2(acc[nf][0], acc[nf][1]);
        *(float2*)&out[((size_t)b * T_SEQ + trow + 8) * 64 + col] =
            make_float2(acc[nf][2], acc[nf][3]);
    }
}

extern "C" void kernel_launch(void* const* d_in, const int* in_sizes, int n_in,
                              void* d_out, int out_size)
{
    const float* x  = (const float*)d_in[0];
    const float* Wq = (const float*)d_in[1];
    const float* Wk = (const float*)d_in[2];
    const float* Wv = (const float*)d_in[3];
    float* out = (float*)d_out;

    qkv_mma<<<dim3(BT / 128), 256>>>(x, Wq, Wk, Wv);
    colstats_mma<<<dim3(T_SEQ / 64, B_SZ), 256>>>();
    vscale_kernel<<<dim3(T_SEQ / 64, B_SZ), 256>>>();
    out_mma<<<dim3(T_SEQ / 128, B_SZ), 256>>>(out);
}

// round 5
// speedup vs baseline: 3.4304x; 1.6216x over previous
#include <cuda_runtime.h>
#include <cuda_bf16.h>

#define B_SZ 8
#define T_SEQ 2048
#define C_DIM 1024
#define H_DIM 64
#define BT (B_SZ * T_SEQ)

// Scratch (u32-packed bf16x2). q is pre-scaled by 0.125.
__device__ unsigned g_qh[BT * 32], g_ql[BT * 32];
__device__ unsigned g_kh[BT * 32], g_kl[BT * 32];
__device__ unsigned g_vth[B_SZ * 64 * (T_SEQ / 2)], g_vtl[B_SZ * 64 * (T_SEQ / 2)]; // [b][h][s/2]
__device__ float g_vraw[BT * 64];
__device__ float g_d[BT];   // column softmax denominators (atomic-accumulated)

__device__ __forceinline__ void mma_bf16(float* c, const unsigned* a, const unsigned* b)
{
    asm volatile(
        "mma.sync.aligned.m16n8k16.row.col.f32.bf16.bf16.f32 "
        "{%0,%1,%2,%3}, {%4,%5,%6,%7}, {%8,%9}, {%0,%1,%2,%3};"
        : "+f"(c[0]), "+f"(c[1]), "+f"(c[2]), "+f"(c[3])
        : "r"(a[0]), "r"(a[1]), "r"(a[2]), "r"(a[3]), "r"(b[0]), "r"(b[1]));
}

__device__ __forceinline__ void split2(float x, float y, unsigned& hi, unsigned& lo)
{
    __nv_bfloat16 xh = __float2bfloat16(x);
    __nv_bfloat16 yh = __float2bfloat16(y);
    float xr = x - __bfloat162float(xh);
    float yr = y - __bfloat162float(yh);
    hi = (unsigned)__bfloat16_as_ushort(xh) | ((unsigned)__bfloat16_as_ushort(yh) << 16);
    lo = (unsigned)__bfloat16_as_ushort(__float2bfloat16(xr)) |
         ((unsigned)__bfloat16_as_ushort(__float2bfloat16(yr)) << 16);
}

__global__ void zero_d_kernel()
{
    int i = blockIdx.x * 256 + threadIdx.x;
    if (i < BT) g_d[i] = 0.f;
}

// ---------------------------------------------------------------------------
// Kernel 1: fused QKV projection. grid = 256 (64-row tiles), block = 256.
// Warp w: m-group w&1 (32 rows), n-group w>>1 (6 n-frags = 48 of 192 cols).
// ---------------------------------------------------------------------------
#define PB 18

__global__ __launch_bounds__(256) void qkv_mma(
    const float* __restrict__ x,
    const float* __restrict__ Wq,
    const float* __restrict__ Wk,
    const float* __restrict__ Wv)
{
    __shared__ unsigned xs_h[64 * PB], xs_l[64 * PB];
    __shared__ unsigned ws_h[192 * PB], ws_l[192 * PB];

    const int tid = threadIdx.x, lane = tid & 31, w = tid >> 5;
    const int g = lane >> 2, t4 = lane & 3;
    const int row0 = blockIdx.x * 64;
    const int mrow = 32 * (w & 1);
    const int nf0 = 6 * (w >> 1);

    float acc[2][6][4];
#pragma unroll
    for (int mt = 0; mt < 2; mt++)
#pragma unroll
        for (int nf = 0; nf < 6; nf++)
#pragma unroll
            for (int e = 0; e < 4; e++) acc[mt][nf][e] = 0.f;

    for (int kc = 0; kc < C_DIM; kc += 32) {
        __syncthreads();
#pragma unroll
        for (int i = 0; i < 2; i++) {
            int e = tid * 4 + i * 1024;
            int r = e >> 5, c = e & 31;
            float4 v = *(const float4*)(x + (size_t)(row0 + r) * C_DIM + kc + c);
            unsigned h0, l0, h1, l1;
            split2(v.x, v.y, h0, l0);
            split2(v.z, v.w, h1, l1);
            xs_h[r * PB + (c >> 1)] = h0; xs_h[r * PB + (c >> 1) + 1] = h1;
            xs_l[r * PB + (c >> 1)] = l0; xs_l[r * PB + (c >> 1) + 1] = l1;
        }
#pragma unroll
        for (int i = 0; i < 6; i++) {
            int e = tid * 4 + i * 1024;
            int r = e >> 5, c = e & 31;
            const float* Wp = (r < 64) ? (Wq + (size_t)r * C_DIM)
                            : (r < 128) ? (Wk + (size_t)(r - 64) * C_DIM)
                                        : (Wv + (size_t)(r - 128) * C_DIM);
            float4 v = *(const float4*)(Wp + kc + c);
            unsigned h0, l0, h1, l1;
            split2(v.x, v.y, h0, l0);
            split2(v.z, v.w, h1, l1);
            ws_h[r * PB + (c >> 1)] = h0; ws_h[r * PB + (c >> 1) + 1] = h1;
            ws_l[r * PB + (c >> 1)] = l0; ws_l[r * PB + (c >> 1) + 1] = l1;
        }
        __syncthreads();

#pragma unroll
        for (int ks = 0; ks < 2; ks++) {
            unsigned ah[2][4], al[2][4];
            int cu = 8 * ks + t4;
#pragma unroll
            for (int mt = 0; mt < 2; mt++) {
                int r = mrow + 16 * mt + g;
                ah[mt][0] = xs_h[r * PB + cu];       ah[mt][1] = xs_h[(r + 8) * PB + cu];
                ah[mt][2] = xs_h[r * PB + cu + 4];   ah[mt][3] = xs_h[(r + 8) * PB + cu + 4];
                al[mt][0] = xs_l[r * PB + cu];       al[mt][1] = xs_l[(r + 8) * PB + cu];
                al[mt][2] = xs_l[r * PB + cu + 4];   al[mt][3] = xs_l[(r + 8) * PB + cu + 4];
            }
#pragma unroll
            for (int nf = 0; nf < 6; nf++) {
                int hrow = 8 * (nf0 + nf) + g;
                unsigned bh[2], bl[2];
                bh[0] = ws_h[hrow * PB + cu]; bh[1] = ws_h[hrow * PB + cu + 4];
                bl[0] = ws_l[hrow * PB + cu]; bl[1] = ws_l[hrow * PB + cu + 4];
#pragma unroll
                for (int mt = 0; mt < 2; mt++) {
                    mma_bf16(acc[mt][nf], ah[mt], bh);
                    mma_bf16(acc[mt][nf], ah[mt], bl);
                    mma_bf16(acc[mt][nf], al[mt], bh);
                }
            }
        }
    }

    // epilogue: q scaled by 0.125 -> hi/lo; k -> hi/lo; v -> fp32
#pragma unroll
    for (int mt = 0; mt < 2; mt++) {
#pragma unroll
        for (int nf = 0; nf < 6; nf++) {
            int col = 8 * (nf0 + nf) + 2 * t4;
            size_t r0g = (size_t)(row0 + mrow + 16 * mt + g);
            float c0 = acc[mt][nf][0], c1 = acc[mt][nf][1];
            float c2 = acc[mt][nf][2], c3 = acc[mt][nf][3];
            if (col < 64) {
                unsigned h, l;
                split2(c0 * 0.125f, c1 * 0.125f, h, l);
                g_qh[r0g * 32 + (col >> 1)] = h; g_ql[r0g * 32 + (col >> 1)] = l;
                split2(c2 * 0.125f, c3 * 0.125f, h, l);
                g_qh[(r0g + 8) * 32 + (col >> 1)] = h; g_ql[(r0g + 8) * 32 + (col >> 1)] = l;
            } else if (col < 128) {
                int kc2 = (col - 64) >> 1;
                unsigned h, l;
                split2(c0, c1, h, l);
                g_kh[r0g * 32 + kc2] = h; g_kl[r0g * 32 + kc2] = l;
                split2(c2, c3, h, l);
                g_kh[(r0g + 8) * 32 + kc2] = h; g_kl[(r0g + 8) * 32 + kc2] = l;
            } else {
                int vc = col - 128;
                *(float2*)&g_vraw[r0g * 64 + vc] = make_float2(c0, c1);
                *(float2*)&g_vraw[(r0g + 8) * 64 + vc] = make_float2(c2, c3);
            }
        }
    }
}

// ---------------------------------------------------------------------------
// Kernel 2: partial column denominators, balanced over (s-tile 64, t-chunk 512).
// grid = (80, B), block = 256. atomicAdd into g_d.
// ---------------------------------------------------------------------------
#define PC 36

__global__ __launch_bounds__(256) void colstats_mma()
{
    __shared__ unsigned ks_h[64 * PC], ks_l[64 * PC];
    __shared__ unsigned qs_h[64 * PC], qs_l[64 * PC];
    __shared__ float red[8][64];

    // map blockIdx.x -> (j = s-tile, c = t-chunk); valid c in [j>>3, 4)
    int j = 0, rem = blockIdx.x;
    for (; j < 32; j++) {
        int cnt = 4 - (j >> 3);
        if (rem < cnt) break;
        rem -= cnt;
    }
    const int c = (j >> 3) + rem;

    const int b = blockIdx.y;
    const int s0 = j * 64;
    const int tid = threadIdx.x, lane = tid & 31, w = tid >> 5;
    const int g = lane >> 2, t4 = lane & 3;
    const int mt = w & 3, nh = w >> 2;

    const unsigned* kh = g_kh + (size_t)b * T_SEQ * 32;
    const unsigned* kl = g_kl + (size_t)b * T_SEQ * 32;
    const unsigned* qh = g_qh + (size_t)b * T_SEQ * 32;
    const unsigned* ql = g_ql + (size_t)b * T_SEQ * 32;

    for (int idx = tid; idx < 2048; idx += 256) {
        int r = idx >> 5, cc = idx & 31;
        ks_h[r * PC + cc] = kh[(size_t)(s0 + r) * 32 + cc];
        ks_l[r * PC + cc] = kl[(size_t)(s0 + r) * 32 + cc];
    }

    float dp[8];
#pragma unroll
    for (int i = 0; i < 8; i++) dp[i] = 0.f;

    const int tt_lo = (j > 8 * c) ? j : 8 * c;
    const int tt_hi = 8 * c + 8;
    for (int tt = tt_lo; tt < tt_hi; tt++) {
        const int t0 = tt * 64;
        __syncthreads();
        for (int idx = tid; idx < 2048; idx += 256) {
            int r = idx >> 5, cc = idx & 31;
            qs_h[r * PC + cc] = qh[(size_t)(t0 + r) * 32 + cc];
            qs_l[r * PC + cc] = ql[(size_t)(t0 + r) * 32 + cc];
        }
        __syncthreads();

        unsigned ah[4][4], al[4][4];
#pragma unroll
        for (int ksi = 0; ksi < 4; ksi++) {
            int r = 16 * mt + g;
            int cu = 8 * ksi + t4;
            ah[ksi][0] = qs_h[r * PC + cu];     ah[ksi][1] = qs_h[(r + 8) * PC + cu];
            ah[ksi][2] = qs_h[r * PC + cu + 4]; ah[ksi][3] = qs_h[(r + 8) * PC + cu + 4];
            al[ksi][0] = qs_l[r * PC + cu];     al[ksi][1] = qs_l[(r + 8) * PC + cu];
            al[ksi][2] = qs_l[r * PC + cu + 4]; al[ksi][3] = qs_l[(r + 8) * PC + cu + 4];
        }

#pragma unroll
        for (int nf = 0; nf < 4; nf++) {
            float S[4] = {0.f, 0.f, 0.f, 0.f};
            int srow = 32 * nh + 8 * nf + g;
#pragma unroll
            for (int ksi = 0; ksi < 4; ksi++) {
                unsigned bh[2], bl[2];
                int cu = 8 * ksi + t4;
                bh[0] = ks_h[srow * PC + cu]; bh[1] = ks_h[srow * PC + cu + 4];
                bl[0] = ks_l[srow * PC + cu]; bl[1] = ks_l[srow * PC + cu + 4];
                mma_bf16(S, ah[ksi], bh);
                mma_bf16(S, ah[ksi], bl);
                mma_bf16(S, al[ksi], bh);
            }
            int scol = s0 + 32 * nh + 8 * nf + 2 * t4;
            int trow = t0 + 16 * mt + g;
            if (trow >= scol)         dp[2 * nf]     += __expf(S[0]);
            if (trow >= scol + 1)     dp[2 * nf + 1] += __expf(S[1]);
            if (trow + 8 >= scol)     dp[2 * nf]     += __expf(S[2]);
            if (trow + 8 >= scol + 1) dp[2 * nf + 1] += __expf(S[3]);
        }
    }

#pragma unroll
    for (int i = 0; i < 8; i++) {
        dp[i] += __shfl_xor_sync(0xffffffffu, dp[i], 4);
        dp[i] += __shfl_xor_sync(0xffffffffu, dp[i], 8);
        dp[i] += __shfl_xor_sync(0xffffffffu, dp[i], 16);
    }
    if (lane < 4) {
#pragma unroll
        for (int nf = 0; nf < 4; nf++) {
            red[w][32 * nh + 8 * nf + 2 * lane]     = dp[2 * nf];
            red[w][32 * nh + 8 * nf + 2 * lane + 1] = dp[2 * nf + 1];
        }
    }
    __syncthreads();
    if (tid < 64) {
        int base = (tid < 32) ? 0 : 4;
        float d = red[base][tid] + red[base + 1][tid] + red[base + 2][tid] + red[base + 3][tid];
        atomicAdd(&g_d[(size_t)b * T_SEQ + s0 + tid], d);
    }
}

// ---------------------------------------------------------------------------
// Kernel 3: v'[s,h] = v[s,h] / d[s], stored transposed [b][h][s] as hi/lo.
// ---------------------------------------------------------------------------
__global__ __launch_bounds__(256) void vscale_kernel()
{
    __shared__ float tile[64][65];
    __shared__ float inv[64];
    const int b = blockIdx.y;
    const int s0 = blockIdx.x * 64;
    const int tid = threadIdx.x;

    if (tid < 64) inv[tid] = 1.0f / g_d[(size_t)b * T_SEQ + s0 + tid];
    __syncthreads();
    for (int idx = tid; idx < 4096; idx += 256) {
        int s = idx >> 6, h = idx & 63;
        tile[s][h] = g_vraw[((size_t)b * T_SEQ + s0 + s) * 64 + h] * inv[s];
    }
    __syncthreads();
    for (int idx = tid; idx < 2048; idx += 256) {
        int h = idx >> 5, sp = idx & 31;
        unsigned hi, lo;
        split2(tile[2 * sp][h], tile[2 * sp + 1][h], hi, lo);
        size_t o = ((size_t)b * 64 + h) * (T_SEQ / 2) + (s0 >> 1) + sp;
        g_vth[o] = hi;
        g_vtl[o] = lo;
    }
}

// ---------------------------------------------------------------------------
// Kernel 4: out partials, balanced over (t-tile 64, s-chunk 256).
// grid = (144, B), block = 128 (4 warps, one m16 tile each). atomicAdd epilogue.
// ---------------------------------------------------------------------------
__global__ __launch_bounds__(128) void out_mma(float* __restrict__ out)
{
    __shared__ unsigned ks_h[64 * PC], ks_l[64 * PC];
    __shared__ unsigned vs_h[64 * PC], vs_l[64 * PC];

    // map blockIdx.x -> (i = t-tile, c = s-chunk); valid c in [0, (i>>2)+1)
    int i = 0, rem = blockIdx.x;
    for (; i < 32; i++) {
        int cnt = (i >> 2) + 1;
        if (rem < cnt) break;
        rem -= cnt;
    }
    const int c = rem;

    const int b = blockIdx.y;
    const int t0 = 64 * i;
    const int tid = threadIdx.x, lane = tid & 31, w = tid >> 5;
    const int g = lane >> 2, t4 = lane & 3;

    const unsigned* qh = g_qh + (size_t)b * T_SEQ * 32;
    const unsigned* ql = g_ql + (size_t)b * T_SEQ * 32;
    const unsigned* kh = g_kh + (size_t)b * T_SEQ * 32;
    const unsigned* kl = g_kl + (size_t)b * T_SEQ * 32;
    const unsigned* vth = g_vth + (size_t)b * 64 * (T_SEQ / 2);
    const unsigned* vtl = g_vtl + (size_t)b * 64 * (T_SEQ / 2);

    const int trow = t0 + 16 * w + g;

    unsigned aqh[4][4], aql[4][4];
#pragma unroll
    for (int ksi = 0; ksi < 4; ksi++) {
        int cu = 8 * ksi + t4;
        aqh[ksi][0] = qh[(size_t)trow * 32 + cu];
        aqh[ksi][1] = qh[(size_t)(trow + 8) * 32 + cu];
        aqh[ksi][2] = qh[(size_t)trow * 32 + cu + 4];
        aqh[ksi][3] = qh[(size_t)(trow + 8) * 32 + cu + 4];
        aql[ksi][0] = ql[(size_t)trow * 32 + cu];
        aql[ksi][1] = ql[(size_t)(trow + 8) * 32 + cu];
        aql[ksi][2] = ql[(size_t)trow * 32 + cu + 4];
        aql[ksi][3] = ql[(size_t)(trow + 8) * 32 + cu + 4];
    }

    float acc[8][4];
#pragma unroll
    for (int nf = 0; nf < 8; nf++)
#pragma unroll
        for (int e = 0; e < 4; e++) acc[nf][e] = 0.f;

    const int st_lo = 4 * c;
    const int st_hi = (4 * c + 3 < i) ? (4 * c + 3) : i;
    for (int st = st_lo; st <= st_hi; st++) {
        const int s0 = 64 * st;
        __syncthreads();
        for (int idx = tid; idx < 2048; idx += 128) {
            int r = idx >> 5, cc = idx & 31;
            ks_h[r * PC + cc] = kh[(size_t)(s0 + r) * 32 + cc];
            ks_l[r * PC + cc] = kl[(size_t)(s0 + r) * 32 + cc];
            vs_h[r * PC + cc] = vth[(size_t)r * (T_SEQ / 2) + (s0 >> 1) + cc];
            vs_l[r * PC + cc] = vtl[(size_t)r * (T_SEQ / 2) + (s0 >> 1) + cc];
        }
        __syncthreads();

        float S[8][4];
#pragma unroll
        for (int nf = 0; nf < 8; nf++) {
#pragma unroll
            for (int e = 0; e < 4; e++) S[nf][e] = 0.f;
            int srow = 8 * nf + g;
#pragma unroll
            for (int ksi = 0; ksi < 4; ksi++) {
                unsigned bh[2], bl[2];
                int cu = 8 * ksi + t4;
                bh[0] = ks_h[srow * PC + cu]; bh[1] = ks_h[srow * PC + cu + 4];
                bl[0] = ks_l[srow * PC + cu]; bl[1] = ks_l[srow * PC + cu + 4];
                mma_bf16(S[nf], aqh[ksi], bh);
                mma_bf16(S[nf], aqh[ksi], bl);
                mma_bf16(S[nf], aql[ksi], bh);
            }
        }

        unsigned ph[4][4], pl[4][4];
#pragma unroll
        for (int fp = 0; fp < 4; fp++) {
#pragma unroll
            for (int half = 0; half < 2; half++) {
                int nf = 2 * fp + half;
                int sc = s0 + 8 * nf + 2 * t4;
                float p0 = (sc     <= trow)     ? __expf(S[nf][0]) : 0.f;
                float p1 = (sc + 1 <= trow)     ? __expf(S[nf][1]) : 0.f;
                float p2 = (sc     <= trow + 8) ? __expf(S[nf][2]) : 0.f;
                float p3 = (sc + 1 <= trow + 8) ? __expf(S[nf][3]) : 0.f;
                unsigned h01, l01, h23, l23;
                split2(p0, p1, h01, l01);
                split2(p2, p3, h23, l23);
                ph[fp][2 * half] = h01; ph[fp][2 * half + 1] = h23;
                pl[fp][2 * half] = l01; pl[fp][2 * half + 1] = l23;
            }
        }

#pragma unroll
        for (int nf = 0; nf < 8; nf++) {
            int hrow = 8 * nf + g;
#pragma unroll
            for (int kp = 0; kp < 4; kp++) {
                unsigned bh[2], bl[2];
                int cu = 8 * kp + t4;
                bh[0] = vs_h[hrow * PC + cu]; bh[1] = vs_h[hrow * PC + cu + 4];
                bl[0] = vs_l[hrow * PC + cu]; bl[1] = vs_l[hrow * PC + cu + 4];
                mma_bf16(acc[nf], ph[kp], bh);
                mma_bf16(acc[nf], ph[kp], bl);
                mma_bf16(acc[nf], pl[kp], bh);
            }
        }
    }

#pragma unroll
    for (int nf = 0; nf < 8; nf++) {
        int col = 8 * nf + 2 * t4;
        float* p0 = &out[((size_t)b * T_SEQ + trow) * 64 + col];
        float* p1 = &out[((size_t)b * T_SEQ + trow + 8) * 64 + col];
        atomicAdd(p0,     acc[nf][0]);
        atomicAdd(p0 + 1, acc[nf][1]);
        atomicAdd(p1,     acc[nf][2]);
        atomicAdd(p1 + 1, acc[nf][3]);
    }
}

extern "C" void kernel_launch(void* const* d_in, const int* in_sizes, int n_in,
                              void* d_out, int out_size)
{
    const float* x  = (const float*)d_in[0];
    const float* Wq = (const float*)d_in[1];
    const float* Wk = (const float*)d_in[2];
    const float* Wv = (const float*)d_in[3];
    float* out = (float*)d_out;

    cudaMemsetAsync(d_out, 0, (size_t)out_size * sizeof(float));
    zero_d_kernel<<<64, 256>>>();
    qkv_mma<<<256, 256>>>(x, Wq, Wk, Wv);
    colstats_mma<<<dim3(80, B_SZ), 256>>>();
    vscale_kernel<<<dim3(T_SEQ / 64, B_SZ), 256>>>();
    out_mma<<<dim3(144, B_SZ), 128>>>(out);
}